// round 11
// baseline (speedup 1.0000x reference)
#include <cuda_runtime.h>
#include <cuda_bf16.h>
#include <cstddef>
#include <cstdint>

#define Bn 8
#define Cc 256
#define Nn 4096      // 64*64 spatial
#define Mm 1024      // 32*32 pooled
#define Dd 32
#define Dv 128

// Scratch (device globals; no allocations allowed)
// g_phi:  (n, j, d) fp32, d permuted per 8-group [0,4,1,5,2,6,3,7]
// g_gp:   (n, v, j) bf16, j-words permuted per 16-j group (same pattern)
__device__ float          g_theta[Bn * Nn * Dd];   // (n, i, d) fp32
__device__ float          g_phi  [Bn * Mm * Dd];
__device__ __nv_bfloat16  g_gp   [Bn * Dv * Mm];

__device__ __forceinline__ void mma_tf32(float c[4], const uint32_t a[4],
                                         uint32_t b0, uint32_t b1) {
    asm volatile("mma.sync.aligned.m16n8k8.row.col.f32.tf32.tf32.f32 "
        "{%0,%1,%2,%3}, {%4,%5,%6,%7}, {%8,%9}, {%0,%1,%2,%3};"
        : "+f"(c[0]), "+f"(c[1]), "+f"(c[2]), "+f"(c[3])
        : "r"(a[0]), "r"(a[1]), "r"(a[2]), "r"(a[3]), "r"(b0), "r"(b1));
}
__device__ __forceinline__ void mma_bf16(float c[4], const uint32_t a[4],
                                         uint32_t b0, uint32_t b1) {
    asm volatile("mma.sync.aligned.m16n8k16.row.col.f32.bf16.bf16.f32 "
        "{%0,%1,%2,%3}, {%4,%5,%6,%7}, {%8,%9}, {%0,%1,%2,%3};"
        : "+f"(c[0]), "+f"(c[1]), "+f"(c[2]), "+f"(c[3])
        : "r"(a[0]), "r"(a[1]), "r"(a[2]), "r"(a[3]), "r"(b0), "r"(b1));
}
__device__ __forceinline__ uint32_t pkbf(float lo, float hi) {
    uint32_t r;
    asm("cvt.rn.bf16x2.f32 %0, %1, %2;" : "=r"(r) : "f"(hi), "f"(lo));
    return r;
}
__device__ __forceinline__ void cp16(void* dst_smem, const void* src) {
    uint32_t d = (uint32_t)__cvta_generic_to_shared(dst_smem);
    asm volatile("cp.async.cg.shared.global [%0], [%1], 16;\n" :: "r"(d), "l"(src));
}
__device__ __forceinline__ void cp_commit() {
    asm volatile("cp.async.commit_group;\n");
}
template<int N> __device__ __forceinline__ void cp_wait() {
    asm volatile("cp.async.wait_group %0;\n" :: "n"(N));
}
__device__ __forceinline__ void pair_bar(int pair) {
    asm volatile("bar.sync %0, 64;" :: "r"(pair + 1) : "memory");
}
// position of element r within its 8-group under [0,4,1,5,2,6,3,7] order
__device__ __forceinline__ int perm8(int r) {
    return (r < 4) ? 2 * r : 2 * (r - 4) + 1;
}

// ---------------------------------------------------------------------------
// Kernel 1: fused projections + maxpool, tf32 MMA, cp.async double-buffered.
// (unchanged from R10; gmem formats identical)
// ---------------------------------------------------------------------------
#define WS  36
#define XSS 136
#define YSS 132

__global__ void __launch_bounds__(256, 3) proj_mma_kernel(
    const float* __restrict__ x,
    const float* __restrict__ theta_w, const float* __restrict__ theta_b,
    const float* __restrict__ phi_w,   const float* __restrict__ phi_b,
    const float* __restrict__ g_w,     const float* __restrict__ g_b)
{
    extern __shared__ float sm[];
    float* Ws = sm;                    // 2 x 64 x 36
    float* Xs = sm + 2 * 64 * WS;      // 2 x 32 x 136
    float* Ys = sm;                    // 64 x 132 (aliases pipeline)

    const int bi  = blockIdx.x;
    const int grp = blockIdx.y;
    const int n   = blockIdx.z;
    const int t   = threadIdx.x;
    const int w   = t >> 5, lane = t & 31;
    const int gq  = lane >> 2, tq = lane & 3;
    const int mrow = (w & 3) * 16;
    const int nc0  = (w >> 2) * 64;
    const int base = bi * 128;

    const float* xb = x + (size_t)n * Cc * Nn;

    auto issue = [&](int kc, int buf) {
        float* Wb = Ws + buf * 64 * WS;
        float* Xb = Xs + buf * 32 * XSS;
#pragma unroll
        for (int it = 0; it < 2; it++) {
            int idx = t + it * 256;
            int r = idx >> 3, kq = (idx & 7) * 4;
            const float* src;
            if (grp == 0) src = (r < 32) ? &theta_w[r * Cc + kc + kq]
                                         : &phi_w[(r - 32) * Cc + kc + kq];
            else          src = &g_w[((grp - 1) * 64 + r) * Cc + kc + kq];
            cp16(&Wb[r * WS + kq], src);
        }
#pragma unroll
        for (int it = 0; it < 4; it++) {
            int idx = t + it * 256;
            int k = idx >> 5, i4 = (idx & 31) * 4;
            cp16(&Xb[k * XSS + i4], &xb[(size_t)(kc + k) * Nn + base + i4]);
        }
        cp_commit();
    };

    float acc[8][4];
#pragma unroll
    for (int nt = 0; nt < 8; nt++)
#pragma unroll
        for (int c = 0; c < 4; c++) acc[nt][c] = 0.f;

    issue(0, 0);
    for (int c8 = 0; c8 < 8; c8++) {
        if (c8 < 7) { issue((c8 + 1) * 32, (c8 + 1) & 1); cp_wait<1>(); }
        else        { cp_wait<0>(); }
        __syncthreads();
        const float* Wb = Ws + (c8 & 1) * 64 * WS;
        const float* Xb = Xs + (c8 & 1) * 32 * XSS;
#pragma unroll
        for (int ks = 0; ks < 4; ks++) {
            uint32_t a[4];
            a[0] = __float_as_uint(Wb[(mrow + gq    ) * WS + ks * 8 + tq    ]);
            a[1] = __float_as_uint(Wb[(mrow + gq + 8) * WS + ks * 8 + tq    ]);
            a[2] = __float_as_uint(Wb[(mrow + gq    ) * WS + ks * 8 + tq + 4]);
            a[3] = __float_as_uint(Wb[(mrow + gq + 8) * WS + ks * 8 + tq + 4]);
#pragma unroll
            for (int nt = 0; nt < 8; nt++) {
                uint32_t b0 = __float_as_uint(Xb[(ks * 8 + tq    ) * XSS + nc0 + nt * 8 + gq]);
                uint32_t b1 = __float_as_uint(Xb[(ks * 8 + tq + 4) * XSS + nc0 + nt * 8 + gq]);
                mma_tf32(acc[nt], a, b0, b1);
            }
        }
        __syncthreads();
    }

    {
        int r0 = mrow + gq, r1 = mrow + gq + 8;
        float b0, b1;
        if (grp == 0) {
            b0 = (r0 < 32) ? theta_b[r0] : phi_b[r0 - 32];
            b1 = (r1 < 32) ? theta_b[r1] : phi_b[r1 - 32];
        } else {
            b0 = g_b[(grp - 1) * 64 + r0];
            b1 = g_b[(grp - 1) * 64 + r1];
        }
#pragma unroll
        for (int nt = 0; nt < 8; nt++) {
            int col = nc0 + nt * 8 + tq * 2;
            *(float2*)&Ys[r0 * YSS + col] = make_float2(acc[nt][0] + b0, acc[nt][1] + b0);
            *(float2*)&Ys[r1 * YSS + col] = make_float2(acc[nt][2] + b1, acc[nt][3] + b1);
        }
    }
    __syncthreads();

    if (grp == 0) {
        for (int idx = t; idx < 32 * 128; idx += 256) {
            int o = idx & 31, i = idx >> 5;
            g_theta[((size_t)n * Nn + base + i) * Dd + o] = Ys[o * YSS + i];
        }
        for (int idx = t; idx < 32 * 32; idx += 256) {
            int o = idx & 31, jw = idx >> 5;
            const float* yr = &Ys[(32 + o) * YSS];
            float m0 = fmaxf(yr[2 * jw],      yr[2 * jw + 1]);
            float m1 = fmaxf(yr[64 + 2 * jw], yr[64 + 2 * jw + 1]);
            int pos = (o & ~7) + perm8(o & 7);
            g_phi[((size_t)n * Mm + bi * 32 + jw) * Dd + pos] = fmaxf(m0, m1);
        }
    } else {
        int vbase = (grp - 1) * 64;
        for (int idx = t; idx < 64 * 32; idx += 256) {
            int jw = idx & 31, v = idx >> 5;
            const float* yr = &Ys[v * YSS];
            float m0 = fmaxf(yr[2 * jw],      yr[2 * jw + 1]);
            float m1 = fmaxf(yr[64 + 2 * jw], yr[64 + 2 * jw + 1]);
            int g16 = jw >> 4, wloc = (jw & 15) >> 1, lo = jw & 1;
            int pos = g16 * 16 + perm8(wloc) * 2 + lo;
            g_gp[((size_t)n * Dv + vbase + v) * Mm + bi * 32 + pos] =
                __float2bfloat16(fmaxf(m0, m1));
        }
    }
}

// ---------------------------------------------------------------------------
// Kernel 2: FUSED attention + out conv, warp-pair split for 24 warps/SM.
// Block = 64 queries, 8 warps = 4 pairs. Pair member u: energy+exp for key
// half u, P.V for v half u, out-conv for channel half u. P/O fragments
// exchanged pair-locally through smem with named barriers.
// grid (64 q-tiles, 8 batches), 256 threads, 3 blocks/SM.
// ---------------------------------------------------------------------------
#define KB    64
#define NKB   (Mm / KB)        // 16
// smem word map (67584 B total):
//   Phs 2 x 64 x 32 fp32 swizzled  [0, 4096)
//   Gsw 2 x 128 x 32 words         [4096, 12288)
//   Xch 4 pairs x 32 lanes x 36 w  [12288, 16896)
//   phase3 Wsw 256 x 64 words aliases [0, 16384)
#define XCHW 36

__global__ void __launch_bounds__(256, 3) attn_fused_kernel(
    const float* __restrict__ x,
    const float* __restrict__ out_w,
    const float* __restrict__ out_b,
    const float* __restrict__ gamma,
    float* __restrict__ out)
{
    extern __shared__ float sm[];
    float* Phs     = sm;
    uint32_t* Gsw  = (uint32_t*)sm + 4096;
    uint32_t* Xch  = (uint32_t*)sm + 12288;
    uint32_t* Wsw  = (uint32_t*)sm;

    const int n  = blockIdx.y;
    const int i0 = blockIdx.x * 64;
    const int t  = threadIdx.x;
    const int w  = t >> 5;
    const int lane = t & 31;
    const int pair = w >> 1;
    const int u    = w & 1;
    const int qb = pair * 16;
    const int gq = lane >> 2;
    const int tq = lane & 3;
    const int swz = (gq & 3) << 3;
    uint32_t* myx = Xch + pair * (32 * XCHW) + lane * XCHW;

    // Q A-fragments (persist)
    uint32_t qa[4][4];
    {
        const float* th = g_theta + ((size_t)n * Nn + i0 + qb) * Dd;
#pragma unroll
        for (int kc = 0; kc < 4; kc++) {
            qa[kc][0] = __float_as_uint(th[(gq    ) * Dd + kc * 8 + tq    ]);
            qa[kc][1] = __float_as_uint(th[(gq + 8) * Dd + kc * 8 + tq    ]);
            qa[kc][2] = __float_as_uint(th[(gq    ) * Dd + kc * 8 + tq + 4]);
            qa[kc][3] = __float_as_uint(th[(gq + 8) * Dd + kc * 8 + tq + 4]);
        }
    }

    auto issue = [&](int chunk) {
        int buf = chunk & 1;
        int jb = chunk * KB;
        float* Pb = Phs + buf * 2048;
        uint32_t* Gb = Gsw + buf * 4096;
#pragma unroll
        for (int it = 0; it < 2; it++) {
            int idx = t + it * 256;                 // phi: 64 j x 8 chunks
            int j = idx >> 3, c = idx & 7;
            int cs = c ^ ((j & 3) << 1);
            cp16(&Pb[j * 32 + cs * 4],
                 &g_phi[((size_t)n * Mm + jb + j) * Dd + c * 4]);
        }
#pragma unroll
        for (int it = 0; it < 4; it++) {
            int idx = t + it * 256;                 // g: 128 v x 8 chunks
            int v = idx >> 3, c = idx & 7;
            int cs = c ^ ((v & 3) << 1);
            cp16(&Gb[v * 32 + cs * 4],
                 &g_gp[((size_t)n * Dv + v) * Mm + jb + c * 8]);
        }
        cp_commit();
    };

    float oacc[8][4];
#pragma unroll
    for (int vt = 0; vt < 8; vt++)
#pragma unroll
        for (int c = 0; c < 4; c++) oacc[vt][c] = 0.f;

    float s0 = 0.f, s1 = 0.f;

    issue(0);
    for (int kb = 0; kb < NKB; kb++) {
        cp_wait<0>();
        __syncthreads();
        if (kb + 1 < NKB) issue(kb + 1);

        const float* Pb = Phs + (kb & 1) * 2048;
        const uint32_t* Gb = Gsw + (kb & 1) * 4096;

        // energy + exp for this warp's key half (32 keys = 2 k16 chunks)
#pragma unroll
        for (int pl = 0; pl < 2; pl++) {
            int nr0 = u * 4 + 2 * pl;
            int nr1 = nr0 + 1;
            float ea[4] = {0.f, 0.f, 0.f, 0.f};
            float eb[4] = {0.f, 0.f, 0.f, 0.f};
#pragma unroll
            for (int kd = 0; kd < 4; kd++) {
                int wi = (kd * 8 + 2 * tq) ^ swz;
                float2 ba = *(const float2*)&Pb[(nr0 * 8 + gq) * 32 + wi];
                mma_tf32(ea, qa[kd], __float_as_uint(ba.x), __float_as_uint(ba.y));
            }
#pragma unroll
            for (int kd = 0; kd < 4; kd++) {
                int wi = (kd * 8 + 2 * tq) ^ swz;
                float2 bb = *(const float2*)&Pb[(nr1 * 8 + gq) * 32 + wi];
                mma_tf32(eb, qa[kd], __float_as_uint(bb.x), __float_as_uint(bb.y));
            }
            ea[0] = __expf(ea[0]); ea[1] = __expf(ea[1]);
            ea[2] = __expf(ea[2]); ea[3] = __expf(ea[3]);
            eb[0] = __expf(eb[0]); eb[1] = __expf(eb[1]);
            eb[2] = __expf(eb[2]); eb[3] = __expf(eb[3]);
            s0 += ea[0] + ea[1] + eb[0] + eb[1];
            s1 += ea[2] + ea[3] + eb[2] + eb[3];
            uint4 pw;
            pw.x = pkbf(ea[0], ea[1]);
            pw.y = pkbf(ea[2], ea[3]);
            pw.z = pkbf(eb[0], eb[1]);
            pw.w = pkbf(eb[2], eb[3]);
            *(uint4*)(myx + (u * 2 + pl) * 4) = pw;   // slot kc = u*2+pl
        }
        pair_bar(pair);   // partner's P fragments visible (BAR drains STS)

        // P.V over ALL 4 k16 chunks, for this warp's v half (64 v)
#pragma unroll
        for (int kc = 0; kc < 4; kc++) {
            uint4 pw = *(const uint4*)(myx + kc * 4);
            uint32_t pa[4] = {pw.x, pw.y, pw.z, pw.w};
#pragma unroll
            for (int vt = 0; vt < 8; vt++) {
                int vr = u * 64 + vt * 8 + gq;
                int wi = (kc * 8 + 2 * tq) ^ swz;
                uint2 bb = *(const uint2*)&Gb[vr * 32 + wi];
                mma_bf16(oacc[vt], pa, bb.x, bb.y);
            }
        }
        // next kb's pa stores are ordered by the block barrier at loop top
    }

    // ---- combine exp-sums: quad reduce, then pair exchange ----
    s0 += __shfl_xor_sync(0xffffffff, s0, 1);
    s0 += __shfl_xor_sync(0xffffffff, s0, 2);
    s1 += __shfl_xor_sync(0xffffffff, s1, 1);
    s1 += __shfl_xor_sync(0xffffffff, s1, 2);
    ((float*)myx)[32 + u] = s0;
    ((float*)myx)[34 + u] = s1;
    pair_bar(pair);
    s0 += ((float*)myx)[33 - u];
    s1 += ((float*)myx)[35 - u];

    // ---- pack normalized O half, exchange to get full-K A-frags ----
    {
        const float inv0 = 1.f / s0;
        const float inv1 = 1.f / s1;
#pragma unroll
        for (int kcl = 0; kcl < 4; kcl++) {
            uint4 ow;
            ow.x = pkbf(oacc[2*kcl  ][0] * inv0, oacc[2*kcl  ][1] * inv0);
            ow.y = pkbf(oacc[2*kcl  ][2] * inv1, oacc[2*kcl  ][3] * inv1);
            ow.z = pkbf(oacc[2*kcl+1][0] * inv0, oacc[2*kcl+1][1] * inv0);
            ow.w = pkbf(oacc[2*kcl+1][2] * inv1, oacc[2*kcl+1][3] * inv1);
            *(uint4*)(myx + (u * 4 + kcl) * 4) = ow;
        }
    }
    pair_bar(pair);
    uint32_t oa[8][4];
#pragma unroll
    for (int kc = 0; kc < 8; kc++) {
        uint4 ow = *(const uint4*)(myx + kc * 4);
        oa[kc][0] = ow.x; oa[kc][1] = ow.y; oa[kc][2] = ow.z; oa[kc][3] = ow.w;
    }
    __syncthreads();   // all pairs done before W pane aliases pipeline smem

    // ---- phase 3: out conv (bf16). Full W pane [256 c x 64 words], swizzled.
    const float gm = gamma[0];
#pragma unroll
    for (int it = 0; it < 32; it++) {
        int idx = t + it * 256;                  // 8192: 256 c x 32 float4
        int r = idx >> 5, v4 = (idx & 31) * 4;
        float4 wv = *(const float4*)&out_w[(size_t)r * Dv + v4];
        int wi0 = v4 >> 1;
        int rs = (r & 3) << 3;
        int w0i = (((wi0     ) & ~7) + perm8((wi0    ) & 7)) ^ rs;
        int w1i = (((wi0 + 1) & ~7) + perm8((wi0 + 1) & 7)) ^ rs;
        Wsw[r * 64 + w0i] = pkbf(wv.x, wv.y);
        Wsw[r * 64 + w1i] = pkbf(wv.z, wv.w);
    }
    __syncthreads();

#pragma unroll
    for (int nt = 0; nt < 16; nt++) {
        float acc[4] = {0.f, 0.f, 0.f, 0.f};
        int cr = u * 128 + nt * 8 + gq;
#pragma unroll
        for (int kc = 0; kc < 8; kc++) {
            int wi = (kc * 8 + 2 * tq) ^ ((gq & 3) << 3);
            uint2 bb = *(const uint2*)&Wsw[cr * 64 + wi];
            mma_bf16(acc, oa[kc], bb.x, bb.y);
        }
        int c0 = u * 128 + nt * 8 + 2 * tq;
        int q0 = i0 + qb + gq;
        float bb0 = out_b[c0], bb1 = out_b[c0 + 1];
        size_t o00 = ((size_t)n * Cc + c0    ) * Nn + q0;
        size_t o10 = ((size_t)n * Cc + c0 + 1) * Nn + q0;
        out[o00]     = gm * (acc[0] + bb0) + x[o00];
        out[o10]     = gm * (acc[1] + bb1) + x[o10];
        out[o00 + 8] = gm * (acc[2] + bb0) + x[o00 + 8];
        out[o10 + 8] = gm * (acc[3] + bb1) + x[o10 + 8];
    }
}

// ---------------------------------------------------------------------------
extern "C" void kernel_launch(void* const* d_in, const int* in_sizes, int n_in,
                              void* d_out, int out_size)
{
    const float* x       = (const float*)d_in[0];
    const float* theta_w = (const float*)d_in[1];
    const float* theta_b = (const float*)d_in[2];
    const float* phi_w   = (const float*)d_in[3];
    const float* phi_b   = (const float*)d_in[4];
    const float* g_w     = (const float*)d_in[5];
    const float* g_b     = (const float*)d_in[6];
    const float* out_w   = (const float*)d_in[7];
    const float* out_b   = (const float*)d_in[8];
    const float* gamma   = (const float*)d_in[9];
    float* out = (float*)d_out;

    const int smem1 = 13312 * 4;   // 53 KB
    const int smem2 = 16896 * 4;   // 67584 B -> 3 blocks/SM

    cudaFuncSetAttribute(proj_mma_kernel,   cudaFuncAttributeMaxDynamicSharedMemorySize, smem1);
    cudaFuncSetAttribute(attn_fused_kernel, cudaFuncAttributeMaxDynamicSharedMemorySize, smem2);

    proj_mma_kernel<<<dim3(32, 3, Bn), 256, smem1>>>(x, theta_w, theta_b,
                                                     phi_w, phi_b, g_w, g_b);
    attn_fused_kernel<<<dim3(64, Bn), 256, smem2>>>(x, out_w, out_b, gamma, out);
}

// round 12
// speedup vs baseline: 1.2271x; 1.2271x over previous
#include <cuda_runtime.h>
#include <cuda_bf16.h>
#include <cstddef>
#include <cstdint>

#define Bn 8
#define Cc 256
#define Nn 4096      // 64*64 spatial
#define Mm 1024      // 32*32 pooled
#define Dd 32
#define Dv 128

// Scratch (device globals; no allocations allowed)
// g_phi:  (n, j, d) fp32, d permuted per 8-group [0,4,1,5,2,6,3,7]
// g_gp:   (n, v, j) bf16, j-words permuted per 16-j group (same pattern)
__device__ float          g_theta[Bn * Nn * Dd];   // (n, i, d) fp32
__device__ float          g_phi  [Bn * Mm * Dd];
__device__ __nv_bfloat16  g_gp   [Bn * Dv * Mm];

__device__ __forceinline__ void mma_tf32(float c[4], const uint32_t a[4],
                                         uint32_t b0, uint32_t b1) {
    asm volatile("mma.sync.aligned.m16n8k8.row.col.f32.tf32.tf32.f32 "
        "{%0,%1,%2,%3}, {%4,%5,%6,%7}, {%8,%9}, {%0,%1,%2,%3};"
        : "+f"(c[0]), "+f"(c[1]), "+f"(c[2]), "+f"(c[3])
        : "r"(a[0]), "r"(a[1]), "r"(a[2]), "r"(a[3]), "r"(b0), "r"(b1));
}
__device__ __forceinline__ void mma_bf16(float c[4], const uint32_t a[4],
                                         uint32_t b0, uint32_t b1) {
    asm volatile("mma.sync.aligned.m16n8k16.row.col.f32.bf16.bf16.f32 "
        "{%0,%1,%2,%3}, {%4,%5,%6,%7}, {%8,%9}, {%0,%1,%2,%3};"
        : "+f"(c[0]), "+f"(c[1]), "+f"(c[2]), "+f"(c[3])
        : "r"(a[0]), "r"(a[1]), "r"(a[2]), "r"(a[3]), "r"(b0), "r"(b1));
}
__device__ __forceinline__ uint32_t pkbf(float lo, float hi) {
    uint32_t r;
    asm("cvt.rn.bf16x2.f32 %0, %1, %2;" : "=r"(r) : "f"(hi), "f"(lo));
    return r;
}
__device__ __forceinline__ void cp16(void* dst_smem, const void* src) {
    uint32_t d = (uint32_t)__cvta_generic_to_shared(dst_smem);
    asm volatile("cp.async.cg.shared.global [%0], [%1], 16;\n" :: "r"(d), "l"(src));
}
__device__ __forceinline__ void cp_commit() {
    asm volatile("cp.async.commit_group;\n");
}
template<int N> __device__ __forceinline__ void cp_wait() {
    asm volatile("cp.async.wait_group %0;\n" :: "n"(N));
}
// position of element r within its 8-group under [0,4,1,5,2,6,3,7] order
__device__ __forceinline__ int perm8(int r) {
    return (r < 4) ? 2 * r : 2 * (r - 4) + 1;
}

// ---------------------------------------------------------------------------
// Kernel 1: fused projections + maxpool, tf32 MMA.
// R12: single-barrier pipeline (wait<0> -> sync -> issue(next) -> consume).
// ---------------------------------------------------------------------------
#define WS  36
#define XSS 136
#define YSS 132

__global__ void __launch_bounds__(256, 3) proj_mma_kernel(
    const float* __restrict__ x,
    const float* __restrict__ theta_w, const float* __restrict__ theta_b,
    const float* __restrict__ phi_w,   const float* __restrict__ phi_b,
    const float* __restrict__ g_w,     const float* __restrict__ g_b)
{
    extern __shared__ float sm[];
    float* Ws = sm;                    // 2 x 64 x 36
    float* Xs = sm + 2 * 64 * WS;      // 2 x 32 x 136
    float* Ys = sm;                    // 64 x 132 (aliases pipeline)

    const int bi  = blockIdx.x;
    const int grp = blockIdx.y;
    const int n   = blockIdx.z;
    const int t   = threadIdx.x;
    const int w   = t >> 5, lane = t & 31;
    const int gq  = lane >> 2, tq = lane & 3;
    const int mrow = (w & 3) * 16;
    const int nc0  = (w >> 2) * 64;
    const int base = bi * 128;

    const float* xb = x + (size_t)n * Cc * Nn;

    auto issue = [&](int c8) {
        int kc = c8 * 32;
        float* Wb = Ws + (c8 & 1) * 64 * WS;
        float* Xb = Xs + (c8 & 1) * 32 * XSS;
#pragma unroll
        for (int it = 0; it < 2; it++) {
            int idx = t + it * 256;
            int r = idx >> 3, kq = (idx & 7) * 4;
            const float* src;
            if (grp == 0) src = (r < 32) ? &theta_w[r * Cc + kc + kq]
                                         : &phi_w[(r - 32) * Cc + kc + kq];
            else          src = &g_w[((grp - 1) * 64 + r) * Cc + kc + kq];
            cp16(&Wb[r * WS + kq], src);
        }
#pragma unroll
        for (int it = 0; it < 4; it++) {
            int idx = t + it * 256;
            int k = idx >> 5, i4 = (idx & 31) * 4;
            cp16(&Xb[k * XSS + i4], &xb[(size_t)(kc + k) * Nn + base + i4]);
        }
        cp_commit();
    };

    float acc[8][4];
#pragma unroll
    for (int nt = 0; nt < 8; nt++)
#pragma unroll
        for (int c = 0; c < 4; c++) acc[nt][c] = 0.f;

    issue(0);
    for (int c8 = 0; c8 < 8; c8++) {
        cp_wait<0>();                  // chunk c8 landed
        __syncthreads();               // all warps past consume of c8-1
        if (c8 + 1 < 8) issue(c8 + 1); // overwrites buffer of c8-1 (free)

        const float* Wb = Ws + (c8 & 1) * 64 * WS;
        const float* Xb = Xs + (c8 & 1) * 32 * XSS;
#pragma unroll
        for (int ks = 0; ks < 4; ks++) {
            uint32_t a[4];
            a[0] = __float_as_uint(Wb[(mrow + gq    ) * WS + ks * 8 + tq    ]);
            a[1] = __float_as_uint(Wb[(mrow + gq + 8) * WS + ks * 8 + tq    ]);
            a[2] = __float_as_uint(Wb[(mrow + gq    ) * WS + ks * 8 + tq + 4]);
            a[3] = __float_as_uint(Wb[(mrow + gq + 8) * WS + ks * 8 + tq + 4]);
#pragma unroll
            for (int nt = 0; nt < 8; nt++) {
                uint32_t b0 = __float_as_uint(Xb[(ks * 8 + tq    ) * XSS + nc0 + nt * 8 + gq]);
                uint32_t b1 = __float_as_uint(Xb[(ks * 8 + tq + 4) * XSS + nc0 + nt * 8 + gq]);
                mma_tf32(acc[nt], a, b0, b1);
            }
        }
    }
    __syncthreads();   // all fragment reads done before Ys aliases pipeline

    {
        int r0 = mrow + gq, r1 = mrow + gq + 8;
        float b0, b1;
        if (grp == 0) {
            b0 = (r0 < 32) ? theta_b[r0] : phi_b[r0 - 32];
            b1 = (r1 < 32) ? theta_b[r1] : phi_b[r1 - 32];
        } else {
            b0 = g_b[(grp - 1) * 64 + r0];
            b1 = g_b[(grp - 1) * 64 + r1];
        }
#pragma unroll
        for (int nt = 0; nt < 8; nt++) {
            int col = nc0 + nt * 8 + tq * 2;
            *(float2*)&Ys[r0 * YSS + col] = make_float2(acc[nt][0] + b0, acc[nt][1] + b0);
            *(float2*)&Ys[r1 * YSS + col] = make_float2(acc[nt][2] + b1, acc[nt][3] + b1);
        }
    }
    __syncthreads();

    if (grp == 0) {
        for (int idx = t; idx < 32 * 128; idx += 256) {
            int o = idx & 31, i = idx >> 5;
            g_theta[((size_t)n * Nn + base + i) * Dd + o] = Ys[o * YSS + i];
        }
        for (int idx = t; idx < 32 * 32; idx += 256) {
            int o = idx & 31, jw = idx >> 5;
            const float* yr = &Ys[(32 + o) * YSS];
            float m0 = fmaxf(yr[2 * jw],      yr[2 * jw + 1]);
            float m1 = fmaxf(yr[64 + 2 * jw], yr[64 + 2 * jw + 1]);
            int pos = (o & ~7) + perm8(o & 7);
            g_phi[((size_t)n * Mm + bi * 32 + jw) * Dd + pos] = fmaxf(m0, m1);
        }
    } else {
        int vbase = (grp - 1) * 64;
        for (int idx = t; idx < 64 * 32; idx += 256) {
            int jw = idx & 31, v = idx >> 5;
            const float* yr = &Ys[v * YSS];
            float m0 = fmaxf(yr[2 * jw],      yr[2 * jw + 1]);
            float m1 = fmaxf(yr[64 + 2 * jw], yr[64 + 2 * jw + 1]);
            int g16 = jw >> 4, wloc = (jw & 15) >> 1, lo = jw & 1;
            int pos = g16 * 16 + perm8(wloc) * 2 + lo;
            g_gp[((size_t)n * Dv + vbase + v) * Mm + bi * 32 + pos] =
                __float2bfloat16(fmaxf(m0, m1));
        }
    }
}

// ---------------------------------------------------------------------------
// Kernel 2: FUSED flash attention + out conv + residual. (R10 structure)
// KB=128, 2-stage pipeline, one barrier/iter; phase 3 W pane loaded once.
// R12: energy ea/eb chains interleaved in one kd loop.
// grid (32 q-tiles, 8 batches), 256 threads = 8 warps x 16 q.
// ---------------------------------------------------------------------------
#define KB    128
#define PHS2  40   // phi [j][d] stride in floats
#define GSW   72   // g [v][j-words] stride in words (64 data + 8 pad)
#define WSTR  72   // W pane row stride in words
#define NSTG  2    // pipeline stages

__global__ void __launch_bounds__(256, 2) attn_fused_kernel(
    const float* __restrict__ x,
    const float* __restrict__ out_w,
    const float* __restrict__ out_b,
    const float* __restrict__ gamma,
    float* __restrict__ out)
{
    extern __shared__ float sm[];
    float* Phs = sm;                                          // 2 x 128 x 40 fp32
    uint32_t* Gsw = (uint32_t*)(sm + NSTG * KB * PHS2);       // 2 x 128 x 72 words
    uint32_t* Wsw = (uint32_t*)sm;                            // phase3: 256 x 72 words

    const int n  = blockIdx.y;
    const int i0 = blockIdx.x * 128;
    const int t  = threadIdx.x;
    const int w  = t >> 5;
    const int lane = t & 31;
    const int qb = w * 16;
    const int gq = lane >> 2;
    const int tq = lane & 3;

    // Q A-fragments (persist)
    uint32_t qa[4][4];
    {
        const float* th = g_theta + ((size_t)n * Nn + i0 + qb) * Dd;
#pragma unroll
        for (int kc = 0; kc < 4; kc++) {
            qa[kc][0] = __float_as_uint(th[(gq    ) * Dd + kc * 8 + tq    ]);
            qa[kc][1] = __float_as_uint(th[(gq + 8) * Dd + kc * 8 + tq    ]);
            qa[kc][2] = __float_as_uint(th[(gq    ) * Dd + kc * 8 + tq + 4]);
            qa[kc][3] = __float_as_uint(th[(gq + 8) * Dd + kc * 8 + tq + 4]);
        }
    }

    auto issue = [&](int chunk) {
        int buf = chunk & 1;
        int jb = chunk * KB;
        float* Pb = Phs + buf * KB * PHS2;
        uint32_t* Gb = Gsw + buf * Dv * GSW;
#pragma unroll
        for (int it = 0; it < 4; it++) {
            int idx = t + it * 256;                 // phi: 128 j x 32 d -> 1024 cp16
            int j = idx >> 3, dq = (idx & 7) * 4;
            cp16(&Pb[j * PHS2 + dq], &g_phi[((size_t)n * Mm + jb + j) * Dd + dq]);
        }
#pragma unroll
        for (int it = 0; it < 8; it++) {
            int idx = t + it * 256;                 // g: 128 v x 128 halfs -> 2048 cp16
            int vv = idx >> 4, p8 = (idx & 15) * 8;
            cp16((__nv_bfloat16*)&Gb[vv * GSW] + p8,
                 &g_gp[((size_t)n * Dv + vv) * Mm + jb + p8]);
        }
        cp_commit();
    };

    float oacc[16][4];
#pragma unroll
    for (int vt = 0; vt < 16; vt++)
#pragma unroll
        for (int c = 0; c < 4; c++) oacc[vt][c] = 0.f;

    float s0 = 0.f, s1 = 0.f;   // running exp-sum partials (reduced at end)

    issue(0);
    for (int kb = 0; kb < Mm / KB; kb++) {
        cp_wait<0>();                       // group kb complete
        __syncthreads();                    // all warps past consume of kb-1
        if (kb + 1 < Mm / KB) issue(kb + 1);

        const float* Pb = Phs + (kb & 1) * KB * PHS2;
        const uint32_t* Gb = Gsw + (kb & 1) * Dv * GSW;

        // per key-pair p (16 keys): energy (8 tf32 MMA, 2 chains interleaved)
        // -> exp -> pack -> PV (16 bf16 MMA)
#pragma unroll
        for (int p = 0; p < 8; p++) {
            float ea[4] = {0.f, 0.f, 0.f, 0.f};
            float eb[4] = {0.f, 0.f, 0.f, 0.f};
#pragma unroll
            for (int kd = 0; kd < 4; kd++) {
                float2 ba = *(const float2*)&Pb[((2*p  ) * 8 + gq) * PHS2 + kd * 8 + 2 * tq];
                float2 bb = *(const float2*)&Pb[((2*p+1) * 8 + gq) * PHS2 + kd * 8 + 2 * tq];
                mma_tf32(ea, qa[kd], __float_as_uint(ba.x), __float_as_uint(ba.y));
                mma_tf32(eb, qa[kd], __float_as_uint(bb.x), __float_as_uint(bb.y));
            }
            ea[0] = __expf(ea[0]); ea[1] = __expf(ea[1]);
            ea[2] = __expf(ea[2]); ea[3] = __expf(ea[3]);
            eb[0] = __expf(eb[0]); eb[1] = __expf(eb[1]);
            eb[2] = __expf(eb[2]); eb[3] = __expf(eb[3]);
            s0 += ea[0] + ea[1] + eb[0] + eb[1];
            s1 += ea[2] + ea[3] + eb[2] + eb[3];
            uint32_t pa[4];
            pa[0] = pkbf(ea[0], ea[1]);
            pa[1] = pkbf(ea[2], ea[3]);
            pa[2] = pkbf(eb[0], eb[1]);
            pa[3] = pkbf(eb[2], eb[3]);
#pragma unroll
            for (int vt = 0; vt < 16; vt++) {
                uint2 bb = *(const uint2*)&Gb[(vt * 8 + gq) * GSW + p * 8 + 2 * tq];
                mma_bf16(oacc[vt], pa, bb.x, bb.y);
            }
        }
    }

    // ---- exp-sum reduce (once) and O pack ----
    s0 += __shfl_xor_sync(0xffffffff, s0, 1);
    s0 += __shfl_xor_sync(0xffffffff, s0, 2);
    s1 += __shfl_xor_sync(0xffffffff, s1, 1);
    s1 += __shfl_xor_sync(0xffffffff, s1, 2);

    uint32_t oa[8][4];
    {
        const float inv0 = 1.f / s0;
        const float inv1 = 1.f / s1;
#pragma unroll
        for (int kc = 0; kc < 8; kc++) {
            oa[kc][0] = pkbf(oacc[2*kc  ][0] * inv0, oacc[2*kc  ][1] * inv0);
            oa[kc][1] = pkbf(oacc[2*kc  ][2] * inv1, oacc[2*kc  ][3] * inv1);
            oa[kc][2] = pkbf(oacc[2*kc+1][0] * inv0, oacc[2*kc+1][1] * inv0);
            oa[kc][3] = pkbf(oacc[2*kc+1][2] * inv1, oacc[2*kc+1][3] * inv1);
        }
    }
    __syncthreads();   // all warps done with pipeline smem before W pane aliasing

    // ---- phase 3: out conv (bf16). Full W pane [256 c x 64 words] loaded once.
    const float gm = gamma[0];

#pragma unroll
    for (int it = 0; it < 32; it++) {
        int idx = t + it * 256;                  // 8192: 256 c x 32 float4
        int r = idx >> 5, v4 = (idx & 31) * 4;
        float4 wv = *(const float4*)&out_w[(size_t)r * Dv + v4];
        uint32_t w0 = pkbf(wv.x, wv.y);
        uint32_t w1 = pkbf(wv.z, wv.w);
        int wi0 = v4 >> 1, wi1 = wi0 + 1;
        Wsw[r * WSTR + (wi0 & ~7) + perm8(wi0 & 7)] = w0;
        Wsw[r * WSTR + (wi1 & ~7) + perm8(wi1 & 7)] = w1;
    }
    __syncthreads();

#pragma unroll
    for (int pass = 0; pass < 4; pass++) {
        const int cbase = pass * 64;
#pragma unroll
        for (int nt = 0; nt < 8; nt++) {
            float acc[4] = {0.f, 0.f, 0.f, 0.f};
#pragma unroll
            for (int kc = 0; kc < 8; kc++) {
                uint2 bb = *(const uint2*)&Wsw[(cbase + nt * 8 + gq) * WSTR + kc * 8 + 2 * tq];
                mma_bf16(acc, oa[kc], bb.x, bb.y);
            }
            int c0 = cbase + nt * 8 + 2 * tq;
            int q0 = i0 + qb + gq;
            float bb0 = out_b[c0], bb1 = out_b[c0 + 1];
            size_t o00 = ((size_t)n * Cc + c0    ) * Nn + q0;
            size_t o10 = ((size_t)n * Cc + c0 + 1) * Nn + q0;
            out[o00]     = gm * (acc[0] + bb0) + x[o00];
            out[o10]     = gm * (acc[1] + bb1) + x[o10];
            out[o00 + 8] = gm * (acc[2] + bb0) + x[o00 + 8];
            out[o10 + 8] = gm * (acc[3] + bb1) + x[o10 + 8];
        }
    }
}

// ---------------------------------------------------------------------------
extern "C" void kernel_launch(void* const* d_in, const int* in_sizes, int n_in,
                              void* d_out, int out_size)
{
    const float* x       = (const float*)d_in[0];
    const float* theta_w = (const float*)d_in[1];
    const float* theta_b = (const float*)d_in[2];
    const float* phi_w   = (const float*)d_in[3];
    const float* phi_b   = (const float*)d_in[4];
    const float* g_w     = (const float*)d_in[5];
    const float* g_b     = (const float*)d_in[6];
    const float* out_w   = (const float*)d_in[7];
    const float* out_b   = (const float*)d_in[8];
    const float* gamma   = (const float*)d_in[9];
    float* out = (float*)d_out;

    const int smem1 = 13312 * 4;   // 53 KB
    // phase1: phi 2*128*40*4 = 40960 + G 2*128*72*4 = 73728 -> 114688 B (112 KB)
    // phase3: W pane 256*72*4 = 73728 B (aliases)
    const int smem2 = 114688;

    cudaFuncSetAttribute(proj_mma_kernel,   cudaFuncAttributeMaxDynamicSharedMemorySize, smem1);
    cudaFuncSetAttribute(attn_fused_kernel, cudaFuncAttributeMaxDynamicSharedMemorySize, smem2);

    proj_mma_kernel<<<dim3(32, 3, Bn), 256, smem1>>>(x, theta_w, theta_b,
                                                     phi_w, phi_b, g_w, g_b);
    attn_fused_kernel<<<dim3(32, Bn), 256, smem2>>>(x, out_w, out_b, gamma, out);
}

// round 13
// speedup vs baseline: 1.2915x; 1.0525x over previous
#include <cuda_runtime.h>
#include <cuda_bf16.h>
#include <cstddef>
#include <cstdint>

#define Bn 8
#define Cc 256
#define Nn 4096      // 64*64 spatial
#define Mm 1024      // 32*32 pooled
#define Dd 32
#define Dv 128

// Scratch (device globals; no allocations allowed)
// g_theta: (n, i, d) fp32 plain
// g_phib:  (n, j, d) bf16, d-words permuted per 16-d group [0,4,1,5,2,6,3,7]
// g_gp:    (n, v, j) bf16, j-words permuted per 16-j group (same pattern)
__device__ float          g_theta[Bn * Nn * Dd];
__device__ __nv_bfloat16  g_phib [Bn * Mm * Dd];
__device__ __nv_bfloat16  g_gp   [Bn * Dv * Mm];

__device__ __forceinline__ void mma_tf32(float c[4], const uint32_t a[4],
                                         uint32_t b0, uint32_t b1) {
    asm volatile("mma.sync.aligned.m16n8k8.row.col.f32.tf32.tf32.f32 "
        "{%0,%1,%2,%3}, {%4,%5,%6,%7}, {%8,%9}, {%0,%1,%2,%3};"
        : "+f"(c[0]), "+f"(c[1]), "+f"(c[2]), "+f"(c[3])
        : "r"(a[0]), "r"(a[1]), "r"(a[2]), "r"(a[3]), "r"(b0), "r"(b1));
}
__device__ __forceinline__ void mma_bf16(float c[4], const uint32_t a[4],
                                         uint32_t b0, uint32_t b1) {
    asm volatile("mma.sync.aligned.m16n8k16.row.col.f32.bf16.bf16.f32 "
        "{%0,%1,%2,%3}, {%4,%5,%6,%7}, {%8,%9}, {%0,%1,%2,%3};"
        : "+f"(c[0]), "+f"(c[1]), "+f"(c[2]), "+f"(c[3])
        : "r"(a[0]), "r"(a[1]), "r"(a[2]), "r"(a[3]), "r"(b0), "r"(b1));
}
__device__ __forceinline__ uint32_t pkbf(float lo, float hi) {
    uint32_t r;
    asm("cvt.rn.bf16x2.f32 %0, %1, %2;" : "=r"(r) : "f"(hi), "f"(lo));
    return r;
}
__device__ __forceinline__ void cp16(void* dst_smem, const void* src) {
    uint32_t d = (uint32_t)__cvta_generic_to_shared(dst_smem);
    asm volatile("cp.async.cg.shared.global [%0], [%1], 16;\n" :: "r"(d), "l"(src));
}
__device__ __forceinline__ void cp_commit() {
    asm volatile("cp.async.commit_group;\n");
}
template<int N> __device__ __forceinline__ void cp_wait() {
    asm volatile("cp.async.wait_group %0;\n" :: "n"(N));
}
// position of element r within its 8-group under [0,4,1,5,2,6,3,7] order
__device__ __forceinline__ int perm8(int r) {
    return (r < 4) ? 2 * r : 2 * (r - 4) + 1;
}

// ---------------------------------------------------------------------------
// Kernel 1: fused projections + maxpool, tf32 MMA, single-barrier pipeline.
// phi now stored bf16 (d-word-permuted); g stored bf16 (j-word-permuted).
// ---------------------------------------------------------------------------
#define WS  36
#define XSS 136
#define YSS 132

__global__ void __launch_bounds__(256, 3) proj_mma_kernel(
    const float* __restrict__ x,
    const float* __restrict__ theta_w, const float* __restrict__ theta_b,
    const float* __restrict__ phi_w,   const float* __restrict__ phi_b,
    const float* __restrict__ g_w,     const float* __restrict__ g_b)
{
    extern __shared__ float sm[];
    float* Ws = sm;                    // 2 x 64 x 36
    float* Xs = sm + 2 * 64 * WS;      // 2 x 32 x 136
    float* Ys = sm;                    // 64 x 132 (aliases pipeline)

    const int bi  = blockIdx.x;
    const int grp = blockIdx.y;
    const int n   = blockIdx.z;
    const int t   = threadIdx.x;
    const int w   = t >> 5, lane = t & 31;
    const int gq  = lane >> 2, tq = lane & 3;
    const int mrow = (w & 3) * 16;
    const int nc0  = (w >> 2) * 64;
    const int base = bi * 128;

    const float* xb = x + (size_t)n * Cc * Nn;

    auto issue = [&](int c8) {
        int kc = c8 * 32;
        float* Wb = Ws + (c8 & 1) * 64 * WS;
        float* Xb = Xs + (c8 & 1) * 32 * XSS;
#pragma unroll
        for (int it = 0; it < 2; it++) {
            int idx = t + it * 256;
            int r = idx >> 3, kq = (idx & 7) * 4;
            const float* src;
            if (grp == 0) src = (r < 32) ? &theta_w[r * Cc + kc + kq]
                                         : &phi_w[(r - 32) * Cc + kc + kq];
            else          src = &g_w[((grp - 1) * 64 + r) * Cc + kc + kq];
            cp16(&Wb[r * WS + kq], src);
        }
#pragma unroll
        for (int it = 0; it < 4; it++) {
            int idx = t + it * 256;
            int k = idx >> 5, i4 = (idx & 31) * 4;
            cp16(&Xb[k * XSS + i4], &xb[(size_t)(kc + k) * Nn + base + i4]);
        }
        cp_commit();
    };

    float acc[8][4];
#pragma unroll
    for (int nt = 0; nt < 8; nt++)
#pragma unroll
        for (int c = 0; c < 4; c++) acc[nt][c] = 0.f;

    issue(0);
    for (int c8 = 0; c8 < 8; c8++) {
        cp_wait<0>();
        __syncthreads();
        if (c8 + 1 < 8) issue(c8 + 1);

        const float* Wb = Ws + (c8 & 1) * 64 * WS;
        const float* Xb = Xs + (c8 & 1) * 32 * XSS;
#pragma unroll
        for (int ks = 0; ks < 4; ks++) {
            uint32_t a[4];
            a[0] = __float_as_uint(Wb[(mrow + gq    ) * WS + ks * 8 + tq    ]);
            a[1] = __float_as_uint(Wb[(mrow + gq + 8) * WS + ks * 8 + tq    ]);
            a[2] = __float_as_uint(Wb[(mrow + gq    ) * WS + ks * 8 + tq + 4]);
            a[3] = __float_as_uint(Wb[(mrow + gq + 8) * WS + ks * 8 + tq + 4]);
#pragma unroll
            for (int nt = 0; nt < 8; nt++) {
                uint32_t b0 = __float_as_uint(Xb[(ks * 8 + tq    ) * XSS + nc0 + nt * 8 + gq]);
                uint32_t b1 = __float_as_uint(Xb[(ks * 8 + tq + 4) * XSS + nc0 + nt * 8 + gq]);
                mma_tf32(acc[nt], a, b0, b1);
            }
        }
    }
    __syncthreads();   // all fragment reads done before Ys aliases pipeline

    {
        int r0 = mrow + gq, r1 = mrow + gq + 8;
        float b0, b1;
        if (grp == 0) {
            b0 = (r0 < 32) ? theta_b[r0] : phi_b[r0 - 32];
            b1 = (r1 < 32) ? theta_b[r1] : phi_b[r1 - 32];
        } else {
            b0 = g_b[(grp - 1) * 64 + r0];
            b1 = g_b[(grp - 1) * 64 + r1];
        }
#pragma unroll
        for (int nt = 0; nt < 8; nt++) {
            int col = nc0 + nt * 8 + tq * 2;
            *(float2*)&Ys[r0 * YSS + col] = make_float2(acc[nt][0] + b0, acc[nt][1] + b0);
            *(float2*)&Ys[r1 * YSS + col] = make_float2(acc[nt][2] + b1, acc[nt][3] + b1);
        }
    }
    __syncthreads();

    if (grp == 0) {
        // theta rows 0..31 -> (n, i, d) fp32
        for (int idx = t; idx < 32 * 128; idx += 256) {
            int o = idx & 31, i = idx >> 5;
            g_theta[((size_t)n * Nn + base + i) * Dd + o] = Ys[o * YSS + i];
        }
        // phi rows 32..63 -> maxpool -> (n, j, d_perm) bf16
        for (int idx = t; idx < 32 * 32; idx += 256) {
            int o = idx & 31, jw = idx >> 5;
            const float* yr = &Ys[(32 + o) * YSS];
            float m0 = fmaxf(yr[2 * jw],      yr[2 * jw + 1]);
            float m1 = fmaxf(yr[64 + 2 * jw], yr[64 + 2 * jw + 1]);
            int chunk = o >> 4, dl = (o & 15) >> 1, lo = o & 1;
            int pos = chunk * 16 + perm8(dl) * 2 + lo;
            g_phib[((size_t)n * Mm + bi * 32 + jw) * Dd + pos] =
                __float2bfloat16(fmaxf(m0, m1));
        }
    } else {
        int vbase = (grp - 1) * 64;
        for (int idx = t; idx < 64 * 32; idx += 256) {
            int jw = idx & 31, v = idx >> 5;
            const float* yr = &Ys[v * YSS];
            float m0 = fmaxf(yr[2 * jw],      yr[2 * jw + 1]);
            float m1 = fmaxf(yr[64 + 2 * jw], yr[64 + 2 * jw + 1]);
            int g16 = jw >> 4, wloc = (jw & 15) >> 1, lo = jw & 1;
            int pos = g16 * 16 + perm8(wloc) * 2 + lo;
            g_gp[((size_t)n * Dv + vbase + v) * Mm + bi * 32 + pos] =
                __float2bfloat16(fmaxf(m0, m1));
        }
    }
}

// ---------------------------------------------------------------------------
// Kernel 2: FUSED flash attention + out conv + residual. ALL-bf16 MMA.
// Energy: bf16 m16n8k16 (2 MMAs per 16q x 8k). KB=128, 2-stage pipeline,
// one barrier/iter; phase 3 W pane loaded once.
// grid (32 q-tiles, 8 batches), 256 threads = 8 warps x 16 q.
// ---------------------------------------------------------------------------
#define KB    128
#define PHH   48   // phi row stride in halfs (32 data + 16 pad) = 24 words
#define GSW   72   // g [v][j-words] stride in words (64 data + 8 pad)
#define WSTR  72   // W pane row stride in words
#define NSTG  2

__global__ void __launch_bounds__(256, 2) attn_fused_kernel(
    const float* __restrict__ x,
    const float* __restrict__ out_w,
    const float* __restrict__ out_b,
    const float* __restrict__ gamma,
    float* __restrict__ out)
{
    extern __shared__ float sm[];
    __nv_bfloat16* Phb = (__nv_bfloat16*)sm;                  // 2 x 128 x 48 halfs
    uint32_t* Gsw = (uint32_t*)sm + NSTG * KB * (PHH / 2);    // 2 x 128 x 72 words
    uint32_t* Wsw = (uint32_t*)sm;                            // phase3: 256 x 72 words

    const int n  = blockIdx.y;
    const int i0 = blockIdx.x * 128;
    const int t  = threadIdx.x;
    const int w  = t >> 5;
    const int lane = t & 31;
    const int qb = w * 16;
    const int gq = lane >> 2;
    const int tq = lane & 3;

    // Q A-fragments, bf16 k16 x 2 chunks (persist)
    uint32_t qa[2][4];
    {
        const float* th = g_theta + ((size_t)n * Nn + i0 + qb) * Dd;
#pragma unroll
        for (int kc = 0; kc < 2; kc++) {
            qa[kc][0] = pkbf(th[(gq    ) * Dd + kc * 16 + 2 * tq],
                             th[(gq    ) * Dd + kc * 16 + 2 * tq + 1]);
            qa[kc][1] = pkbf(th[(gq + 8) * Dd + kc * 16 + 2 * tq],
                             th[(gq + 8) * Dd + kc * 16 + 2 * tq + 1]);
            qa[kc][2] = pkbf(th[(gq    ) * Dd + kc * 16 + 8 + 2 * tq],
                             th[(gq    ) * Dd + kc * 16 + 8 + 2 * tq + 1]);
            qa[kc][3] = pkbf(th[(gq + 8) * Dd + kc * 16 + 8 + 2 * tq],
                             th[(gq + 8) * Dd + kc * 16 + 8 + 2 * tq + 1]);
        }
    }

    auto issue = [&](int chunk) {
        int buf = chunk & 1;
        int jb = chunk * KB;
        __nv_bfloat16* Pb = Phb + buf * KB * PHH;
        uint32_t* Gb = Gsw + buf * Dv * GSW;
#pragma unroll
        for (int it = 0; it < 2; it++) {
            int idx = t + it * 256;                 // phi: 128 j x 32 halfs -> 512 cp16
            int j = idx >> 2, c = idx & 3;
            cp16(&Pb[j * PHH + c * 8],
                 &g_phib[((size_t)n * Mm + jb + j) * Dd + c * 8]);
        }
#pragma unroll
        for (int it = 0; it < 8; it++) {
            int idx = t + it * 256;                 // g: 128 v x 128 halfs -> 2048 cp16
            int vv = idx >> 4, p8 = (idx & 15) * 8;
            cp16((__nv_bfloat16*)&Gb[vv * GSW] + p8,
                 &g_gp[((size_t)n * Dv + vv) * Mm + jb + p8]);
        }
        cp_commit();
    };

    float oacc[16][4];
#pragma unroll
    for (int vt = 0; vt < 16; vt++)
#pragma unroll
        for (int c = 0; c < 4; c++) oacc[vt][c] = 0.f;

    float s0 = 0.f, s1 = 0.f;

    issue(0);
    for (int kb = 0; kb < Mm / KB; kb++) {
        cp_wait<0>();
        __syncthreads();
        if (kb + 1 < Mm / KB) issue(kb + 1);

        const uint32_t* Pw = (const uint32_t*)(Phb + (kb & 1) * KB * PHH);
        const uint32_t* Gb = Gsw + (kb & 1) * Dv * GSW;

        // per key-pair p (16 keys): energy (4 bf16 MMA) -> exp -> pack -> PV (16 bf16 MMA)
#pragma unroll
        for (int p = 0; p < 8; p++) {
            float ea[4] = {0.f, 0.f, 0.f, 0.f};
            float eb[4] = {0.f, 0.f, 0.f, 0.f};
#pragma unroll
            for (int kc = 0; kc < 2; kc++) {
                uint2 ba = *(const uint2*)&Pw[((2*p  ) * 8 + gq) * (PHH/2) + kc * 8 + 2 * tq];
                uint2 bb = *(const uint2*)&Pw[((2*p+1) * 8 + gq) * (PHH/2) + kc * 8 + 2 * tq];
                mma_bf16(ea, qa[kc], ba.x, ba.y);
                mma_bf16(eb, qa[kc], bb.x, bb.y);
            }
            ea[0] = __expf(ea[0]); ea[1] = __expf(ea[1]);
            ea[2] = __expf(ea[2]); ea[3] = __expf(ea[3]);
            eb[0] = __expf(eb[0]); eb[1] = __expf(eb[1]);
            eb[2] = __expf(eb[2]); eb[3] = __expf(eb[3]);
            s0 += ea[0] + ea[1] + eb[0] + eb[1];
            s1 += ea[2] + ea[3] + eb[2] + eb[3];
            uint32_t pa[4];
            pa[0] = pkbf(ea[0], ea[1]);
            pa[1] = pkbf(ea[2], ea[3]);
            pa[2] = pkbf(eb[0], eb[1]);
            pa[3] = pkbf(eb[2], eb[3]);
#pragma unroll
            for (int vt = 0; vt < 16; vt++) {
                uint2 bb = *(const uint2*)&Gb[(vt * 8 + gq) * GSW + p * 8 + 2 * tq];
                mma_bf16(oacc[vt], pa, bb.x, bb.y);
            }
        }
    }

    // ---- exp-sum reduce (once) and O pack ----
    s0 += __shfl_xor_sync(0xffffffff, s0, 1);
    s0 += __shfl_xor_sync(0xffffffff, s0, 2);
    s1 += __shfl_xor_sync(0xffffffff, s1, 1);
    s1 += __shfl_xor_sync(0xffffffff, s1, 2);

    uint32_t oa[8][4];
    {
        const float inv0 = 1.f / s0;
        const float inv1 = 1.f / s1;
#pragma unroll
        for (int kc = 0; kc < 8; kc++) {
            oa[kc][0] = pkbf(oacc[2*kc  ][0] * inv0, oacc[2*kc  ][1] * inv0);
            oa[kc][1] = pkbf(oacc[2*kc  ][2] * inv1, oacc[2*kc  ][3] * inv1);
            oa[kc][2] = pkbf(oacc[2*kc+1][0] * inv0, oacc[2*kc+1][1] * inv0);
            oa[kc][3] = pkbf(oacc[2*kc+1][2] * inv1, oacc[2*kc+1][3] * inv1);
        }
    }
    __syncthreads();   // all warps done with pipeline smem before W pane aliasing

    // ---- phase 3: out conv (bf16). Full W pane [256 c x 64 words] loaded once.
    const float gm = gamma[0];

#pragma unroll
    for (int it = 0; it < 32; it++) {
        int idx = t + it * 256;                  // 8192: 256 c x 32 float4
        int r = idx >> 5, v4 = (idx & 31) * 4;
        float4 wv = *(const float4*)&out_w[(size_t)r * Dv + v4];
        uint32_t w0 = pkbf(wv.x, wv.y);
        uint32_t w1 = pkbf(wv.z, wv.w);
        int wi0 = v4 >> 1, wi1 = wi0 + 1;
        Wsw[r * WSTR + (wi0 & ~7) + perm8(wi0 & 7)] = w0;
        Wsw[r * WSTR + (wi1 & ~7) + perm8(wi1 & 7)] = w1;
    }
    __syncthreads();

#pragma unroll
    for (int pass = 0; pass < 4; pass++) {
        const int cbase = pass * 64;
#pragma unroll
        for (int nt = 0; nt < 8; nt++) {
            float acc[4] = {0.f, 0.f, 0.f, 0.f};
#pragma unroll
            for (int kc = 0; kc < 8; kc++) {
                uint2 bb = *(const uint2*)&Wsw[(cbase + nt * 8 + gq) * WSTR + kc * 8 + 2 * tq];
                mma_bf16(acc, oa[kc], bb.x, bb.y);
            }
            int c0 = cbase + nt * 8 + 2 * tq;
            int q0 = i0 + qb + gq;
            float bb0 = out_b[c0], bb1 = out_b[c0 + 1];
            size_t o00 = ((size_t)n * Cc + c0    ) * Nn + q0;
            size_t o10 = ((size_t)n * Cc + c0 + 1) * Nn + q0;
            out[o00]     = gm * (acc[0] + bb0) + x[o00];
            out[o10]     = gm * (acc[1] + bb1) + x[o10];
            out[o00 + 8] = gm * (acc[2] + bb0) + x[o00 + 8];
            out[o10 + 8] = gm * (acc[3] + bb1) + x[o10 + 8];
        }
    }
}

// ---------------------------------------------------------------------------
extern "C" void kernel_launch(void* const* d_in, const int* in_sizes, int n_in,
                              void* d_out, int out_size)
{
    const float* x       = (const float*)d_in[0];
    const float* theta_w = (const float*)d_in[1];
    const float* theta_b = (const float*)d_in[2];
    const float* phi_w   = (const float*)d_in[3];
    const float* phi_b   = (const float*)d_in[4];
    const float* g_w     = (const float*)d_in[5];
    const float* g_b     = (const float*)d_in[6];
    const float* out_w   = (const float*)d_in[7];
    const float* out_b   = (const float*)d_in[8];
    const float* gamma   = (const float*)d_in[9];
    float* out = (float*)d_out;

    const int smem1 = 13312 * 4;   // 53 KB
    // phase1: phi 2*128*48*2 = 24576 B + G 2*128*72*4 = 73728 B -> 98304 B (96 KB)
    // phase3: W pane 256*72*4 = 73728 B (aliases)
    const int smem2 = 98304;

    cudaFuncSetAttribute(proj_mma_kernel,   cudaFuncAttributeMaxDynamicSharedMemorySize, smem1);
    cudaFuncSetAttribute(attn_fused_kernel, cudaFuncAttributeMaxDynamicSharedMemorySize, smem2);

    proj_mma_kernel<<<dim3(32, 3, Bn), 256, smem1>>>(x, theta_w, theta_b,
                                                     phi_w, phi_b, g_w, g_b);
    attn_fused_kernel<<<dim3(32, Bn), 256, smem2>>>(x, out_w, out_b, gamma, out);
}